// round 16
// baseline (speedup 1.0000x reference)
#include <cuda_runtime.h>
#include <cuda_fp16.h>
#include <math.h>

#define NB 2048
#define NT 256

typedef unsigned int u32;
typedef unsigned short u16;

// element strides
#define X_LD 264     // fp16 tiles [64][264]
#define AB_LD 72     // fp16 A_hat
#define AST_LD 66    // fp16 staged Ast

// smem byte offsets
#define X0_OFF 0             // X (LN output / layer input)     33792
#define X1_OFF 33792         // qk, then agg output (ping-pong) 33792
#define ABH_OFF 67584        // 64*72*2 = 9216
#define AST_OFF 76800        // 2 layers * 64*66*2 = 16896
#define PART_OFF 93696       // softmax partial sums: 64*2 float = 512
#define P2_OFF 94720         // LN partials: 64*8 float2 = 4096
#define P3_OFF 98816         // LN mean/rstd: 64 float2 = 512
#define SMEM_BYTES 99328

__device__ float g_Ast[2 * 64 * 64];
// fragment-packed fp16 weights: index (((o8*8 + kp)*32 + lane)) uint4;
// .x/.y = kstep0 b0/b1, .z/.w = kstep1. [layer][qk|fc][hi|lo]
__device__ uint4 g_Wf[2][2][2][8192];

// ---------------- PTX wrappers ----------------
__device__ __forceinline__ u32 smem_u32(const void* p) {
    u32 a;
    asm("{ .reg .u64 t; cvta.to.shared.u64 t, %1; cvt.u32.u64 %0, t; }" : "=r"(a) : "l"(p));
    return a;
}
__device__ __forceinline__ void ldmx4(u32 a, u32 r[4]) {
    asm volatile("ldmatrix.sync.aligned.m8n8.x4.shared.b16 {%0,%1,%2,%3}, [%4];"
                 : "=r"(r[0]), "=r"(r[1]), "=r"(r[2]), "=r"(r[3]) : "r"(a));
}
__device__ __forceinline__ void ldmx4t(u32 a, u32 r[4]) {
    asm volatile("ldmatrix.sync.aligned.m8n8.x4.trans.shared.b16 {%0,%1,%2,%3}, [%4];"
                 : "=r"(r[0]), "=r"(r[1]), "=r"(r[2]), "=r"(r[3]) : "r"(a));
}
__device__ __forceinline__ void mma16816(float* d, const u32 a[4], u32 b0, u32 b1) {
    asm volatile("mma.sync.aligned.m16n8k16.row.col.f32.f16.f16.f32 "
                 "{%0,%1,%2,%3}, {%4,%5,%6,%7}, {%8,%9}, {%0,%1,%2,%3};"
                 : "+f"(d[0]), "+f"(d[1]), "+f"(d[2]), "+f"(d[3])
                 : "r"(a[0]), "r"(a[1]), "r"(a[2]), "r"(a[3]), "r"(b0), "r"(b1));
}

__device__ __forceinline__ u32 pack_h2(float v0, float v1) {
    __half2 h = __floats2half2_rn(v0, v1);
    return *(u32*)&h;
}

// ---------------- weight GEMM: C[64 n][256 o], 8 warps, warp tile 64n x 32o ----------------
// acc layout: acc[(nf*4 + of)*4 + j], nf = 16n frag, of = 8o frag.
// Software-pipelined: per k-step, batch all 4 A-fragment LDSMs, then 16 MMAs.
__device__ __forceinline__ void wgemm_reg(
    u32 smb, u32 x_off, const uint4* __restrict__ wH,
    float* acc, int warp, int lane)
{
#pragma unroll
    for (int i = 0; i < 64; i++) acc[i] = 0.f;

    int arow = lane & 15;
    int acol = 8 * (lane >> 4);
    u32 fb = (u32)((warp * 4 * 8) * 32 + lane);  // of stride = 8*32 = 256

    uint4 bh[4];
#pragma unroll
    for (int of = 0; of < 4; of++) bh[of] = wH[fb + of * 256];

#pragma unroll
    for (int kp = 0; kp < 8; kp++) {
        // ---- ks = 0 ----
        {
            int kg = kp * 32;
            u32 ah[4][4];
#pragma unroll
            for (int nf = 0; nf < 4; nf++)
                ldmx4(smb + x_off + (u32)((nf * 16 + arow) * X_LD + kg + acol) * 2, ah[nf]);
#pragma unroll
            for (int nf = 0; nf < 4; nf++)
#pragma unroll
                for (int of = 0; of < 4; of++)
                    mma16816(acc + (nf * 4 + of) * 4, ah[nf], bh[of].x, bh[of].y);
        }
        uint4 nh[4];
        if (kp < 7) {
#pragma unroll
            for (int of = 0; of < 4; of++) nh[of] = wH[fb + of * 256 + (kp + 1) * 32];
        }
        // ---- ks = 1 ----
        {
            int kg = kp * 32 + 16;
            u32 ah[4][4];
#pragma unroll
            for (int nf = 0; nf < 4; nf++)
                ldmx4(smb + x_off + (u32)((nf * 16 + arow) * X_LD + kg + acol) * 2, ah[nf]);
#pragma unroll
            for (int nf = 0; nf < 4; nf++)
#pragma unroll
                for (int of = 0; of < 4; of++)
                    mma16816(acc + (nf * 4 + of) * 4, ah[nf], bh[of].z, bh[of].w);
        }
        if (kp < 7) {
#pragma unroll
            for (int of = 0; of < 4; of++) bh[of] = nh[of];
        }
    }
}

// store acc as fp16 tiles (qk / agg epilogues; col base = warp*32)
__device__ __forceinline__ void wstore_hi(
    char* smc, const float* acc, u32 hoff, int ld, int warp, int lane)
{
    int rb = lane >> 2;
    int cb = warp * 32 + 2 * (lane & 3);
#pragma unroll
    for (int nf = 0; nf < 4; nf++)
#pragma unroll
        for (int of = 0; of < 4; of++)
#pragma unroll
            for (int rr = 0; rr < 2; rr++) {
                int r = nf * 16 + rb + rr * 8;
                int c = cb + of * 8;
                const float* a = acc + (nf * 4 + of) * 4;
                *(u32*)(smc + hoff + (u32)(r * ld + c) * 2) =
                    pack_h2(a[rr * 2], a[rr * 2 + 1]);
            }
}

// store acc + bias directly to global (fc epilogue, layer 1)
__device__ __forceinline__ void wstore_global(
    const float* acc, float* __restrict__ og,
    const float* __restrict__ bias, int warp, int lane)
{
    int rb = lane >> 2;
    int cb = warp * 32 + 2 * (lane & 3);
    float bv[4][2];
#pragma unroll
    for (int of = 0; of < 4; of++) {
        bv[of][0] = bias[cb + of * 8];
        bv[of][1] = bias[cb + of * 8 + 1];
    }
#pragma unroll
    for (int nf = 0; nf < 4; nf++)
#pragma unroll
        for (int of = 0; of < 4; of++)
#pragma unroll
            for (int rr = 0; rr < 2; rr++) {
                int r = nf * 16 + rb + rr * 8;
                int c = cb + of * 8;
                const float* a = acc + (nf * 4 + of) * 4;
                float2 p;
                p.x = a[rr * 2] + bv[of][0];
                p.y = a[rr * 2 + 1] + bv[of][1];
                *(float2*)(og + r * 256 + c) = p;
            }
}

// ---------------- scores: C[64 n][64 m] = q @ k^T, 8 warps, tile 16n x 32m ----------------
__device__ __forceinline__ void scores_tc(u32 smb, float sacc[4][4], int warp, int lane)
{
    int n0 = (warp & 3) * 16;
    int m0 = (warp >> 2) * 32;
#pragma unroll
    for (int t = 0; t < 4; t++)
#pragma unroll
        for (int j = 0; j < 4; j++) sacc[t][j] = 0.f;
    int arow = n0 + (lane & 15);
    int acolsel = 8 * (lane >> 4);
    int brow0 = m0 + (lane & 7) + 8 * ((lane >> 4) & 1);
    int bksel = 8 * ((lane >> 3) & 1);
#pragma unroll
    for (int ks = 0; ks < 8; ks++) {
        int kg = ks * 16;
        u32 ah[4], bh0[4], bh1[4];
        ldmx4(smb + X1_OFF + (u32)(arow * X_LD + kg + acolsel) * 2, ah);
        ldmx4(smb + X1_OFF + (u32)(brow0 * X_LD + 128 + kg + bksel) * 2, bh0);
        ldmx4(smb + X1_OFF + (u32)((brow0 + 16) * X_LD + 128 + kg + bksel) * 2, bh1);
        mma16816(sacc[0], ah, bh0[0], bh0[1]);
        mma16816(sacc[1], ah, bh0[2], bh0[3]);
        mma16816(sacc[2], ah, bh1[0], bh1[1]);
        mma16816(sacc[3], ah, bh1[2], bh1[3]);
    }
}

// ---------------- agg: C[64 n][256 d] = A_hat @ X0, warp tile 64n x 32d ----------------
__device__ __forceinline__ void agg_tc(char* smc, u32 smb, float* acc,
                                       int warp, int lane)
{
#pragma unroll
    for (int i = 0; i < 64; i++) acc[i] = 0.f;
    int arow = lane & 15;
    int acol = 8 * (lane >> 4);
    int xrow = lane & 15;
    int xcol = warp * 32 + 8 * (lane >> 4);
#pragma unroll
    for (int ks = 0; ks < 4; ks++) {
        int kg = ks * 16;
        u32 ah[4][4];
#pragma unroll
        for (int nf = 0; nf < 4; nf++)
            ldmx4(smb + ABH_OFF + (u32)((nf * 16 + arow) * AB_LD + kg + acol) * 2, ah[nf]);
#pragma unroll
        for (int dg = 0; dg < 2; dg++) {
            u32 bh[4];
            ldmx4t(smb + X0_OFF + (u32)((kg + xrow) * X_LD + xcol + dg * 16) * 2, bh);
#pragma unroll
            for (int nf = 0; nf < 4; nf++) {
                mma16816(acc + (nf * 4 + dg * 2) * 4, ah[nf], bh[0], bh[1]);
                mma16816(acc + (nf * 4 + dg * 2 + 1) * 4, ah[nf], bh[2], bh[3]);
            }
        }
    }
}

// ---------------- LayerNorm (global fp32 source) -> fp16 X0 tile ----------------
__device__ __forceinline__ void ln_global(
    char* smc, const float* __restrict__ src,
    const float* __restrict__ gg, const float* __restrict__ bb, int tid)
{
    int warp = tid >> 5, lane = tid & 31;
    for (int n = warp; n < 64; n += 8) {
        const float* row = src + (size_t)n * 256;
        float v[8];
        float s = 0.f, sq = 0.f;
#pragma unroll
        for (int i = 0; i < 4; i++) {
            int c = 2 * lane + 64 * i;
            float2 t = *(const float2*)(row + c);
            v[2 * i] = t.x; v[2 * i + 1] = t.y;
            s += t.x + t.y;
            sq += t.x * t.x + t.y * t.y;
        }
#pragma unroll
        for (int off = 16; off > 0; off >>= 1) {
            s += __shfl_xor_sync(0xffffffffu, s, off);
            sq += __shfl_xor_sync(0xffffffffu, sq, off);
        }
        float mean = s * (1.0f / 256.0f);
        float var = sq * (1.0f / 256.0f) - mean * mean;
        float rstd = rsqrtf(var + 1e-5f);
#pragma unroll
        for (int i = 0; i < 4; i++) {
            int c = 2 * lane + 64 * i;
            float o0 = (v[2 * i] - mean) * rstd * gg[c] + bb[c];
            float o1 = (v[2 * i + 1] - mean) * rstd * gg[c + 1] + bb[c + 1];
            *(u32*)(smc + X0_OFF + (u32)(n * X_LD + c) * 2) = pack_h2(o0, o1);
        }
    }
}

// stage both layers' Ast into smem as fp16
__device__ __forceinline__ void stage_ast(char* smc, int tid) {
    u16* dst = (u16*)(smc + AST_OFF);
    for (int i = tid; i < 8192; i += NT) {
        int l = i >> 12, j = i & 4095;
        int r = j >> 6, m = j & 63;
        dst[l * 64 * AST_LD + r * AST_LD + m] =
            __half_as_ushort(__float2half_rn(g_Ast[l * 4096 + j]));
    }
}

// ---------------- prologue: weights (fragment-packed fp16 hi/lo) + adj softmax ----------------
__global__ void prep_kernel(
    const float* __restrict__ th0, const float* __restrict__ ph0, const float* __restrict__ fcw0,
    const float* __restrict__ th1, const float* __restrict__ ph1, const float* __restrict__ fcw1,
    const float* __restrict__ adj0, const float* __restrict__ adj1)
{
    if (blockIdx.x >= 512) {
        int gw = (blockIdx.x - 512) * 16 + (threadIdx.x >> 5);
        int lane = threadIdx.x & 31;
        int mat = gw >> 6, r = gw & 63;
        const float* row = (mat ? adj1 : adj0) + r * 64;
        float v0 = row[lane], v1 = row[32 + lane];
        float mx = fmaxf(v0, v1);
#pragma unroll
        for (int off = 16; off > 0; off >>= 1)
            mx = fmaxf(mx, __shfl_xor_sync(0xffffffffu, mx, off));
        float e0 = __expf(v0 - mx), e1 = __expf(v1 - mx);
        float ss = e0 + e1;
#pragma unroll
        for (int off = 16; off > 0; off >>= 1)
            ss += __shfl_xor_sync(0xffffffffu, ss, off);
        float inv = 1.0f / ss;
        float* dst = g_Ast + mat * 4096 + r * 64;
        dst[lane] = e0 * inv;
        dst[32 + lane] = e1 * inv;
        return;
    }
    int idx = blockIdx.x * 512 + threadIdx.x;  // 0..262143
    int k = idx & 255, r = (idx >> 8) & 255, g = (idx >> 16) & 1, l = idx >> 17;
    const float* th = l ? th1 : th0;
    const float* pw = l ? ph1 : ph0;
    const float* fw = l ? fcw1 : fcw0;
    float v;
    if (g == 0) v = (r < 128) ? th[r * 256 + k] : pw[(r - 128) * 256 + k];
    else        v = fw[r * 256 + k];
    __half hb = __float2half_rn(v);
    __half lb = __float2half_rn(v - __half2float(hb));
    u32 o8 = (u32)(r >> 3);
    u32 kp = (u32)(k >> 5);
    u32 lane = (u32)((r & 7) * 4 + ((k >> 1) & 3));
    u32 slot = (u32)(((k >> 4) & 1) * 2 + ((k >> 3) & 1));
    u32 off16 = ((((o8 * 8 + kp) * 32 + lane) * 4 + slot) << 1) | (u32)(k & 1);
    ((u16*)g_Wf[l][g][0])[off16] = __half_as_ushort(hb);
    ((u16*)g_Wf[l][g][1])[off16] = __half_as_ushort(lb);
}

// ---------------- main kernel: 256 threads, 2 CTAs/SM ----------------
__global__ void __launch_bounds__(NT, 2) gconv_kernel(
    const float* __restrict__ graph,
    const float* __restrict__ ln_in_g, const float* __restrict__ ln_in_b,
    const float* __restrict__ fcb0,
    const float* __restrict__ ln0_g, const float* __restrict__ ln0_b,
    const float* __restrict__ fcb1,
    float* __restrict__ out)
{
    extern __shared__ char smc[];
    u32 smb = smem_u32(smc);
    int tid = threadIdx.x;
    int warp = tid >> 5, lane = tid & 31;
    int b = blockIdx.x;

    // input LN -> X0; stage both Ast layers
    ln_global(smc, graph + (size_t)b * 64 * 256, ln_in_g, ln_in_b, tid);
    stage_ast(smc, tid);
    __syncthreads();

    float acc[64];

#pragma unroll 1
    for (int l = 0; l < 2; l++) {
        // ---- qk = X0 @ W_qk^T -> X1 ----
        wgemm_reg(smb, X0_OFF, g_Wf[l][0][0], acc, warp, lane);
        wstore_hi(smc, acc, X1_OFF, X_LD, warp, lane);
        __syncthreads();

        // ---- scores (reads X1) + max-free softmax -> A_hat fp16 (ABH) ----
        // LN-bounded inputs => |score| <= ~12, exp() safe without max-shift.
        {
            float sacc[4][4];
            scores_tc(smb, sacc, warp, lane);
            const float sscale = 0.08838834764831845f;  // 1/sqrt(128)
            float s0 = 0.f, s1 = 0.f;
#pragma unroll
            for (int t = 0; t < 4; t++) {
                sacc[t][0] = __expf(sacc[t][0] * sscale);
                sacc[t][1] = __expf(sacc[t][1] * sscale);
                sacc[t][2] = __expf(sacc[t][2] * sscale);
                sacc[t][3] = __expf(sacc[t][3] * sscale);
                s0 += sacc[t][0] + sacc[t][1];
                s1 += sacc[t][2] + sacc[t][3];
            }
#pragma unroll
            for (int d = 1; d <= 2; d <<= 1) {
                s0 += __shfl_xor_sync(0xffffffffu, s0, d);
                s1 += __shfl_xor_sync(0xffffffffu, s1, d);
            }
            int n0 = (warp & 3) * 16;
            int mw = warp >> 2;
            int r = n0 + (lane >> 2);
            float* part = (float*)(smc + PART_OFF);
            if ((lane & 3) == 0) {
                part[r * 2 + mw] = s0;
                part[(r + 8) * 2 + mw] = s1;
            }
            // prefetch Ast rows while waiting on the barrier
            int m0 = mw * 32;
            const u16* ast = (const u16*)(smc + AST_OFF) + l * 64 * AST_LD;
            u32 av0[4], av1[4];
#pragma unroll
            for (int t = 0; t < 4; t++) {
                int m = m0 + 2 * (lane & 3) + t * 8;
                av0[t] = *(const u32*)(ast + r * AST_LD + m);
                av1[t] = *(const u32*)(ast + (r + 8) * AST_LD + m);
            }
            __syncthreads();
            float corr0 = 1.0f / (part[r * 2] + part[r * 2 + 1]);
            float corr1 = 1.0f / (part[(r + 8) * 2] + part[(r + 8) * 2 + 1]);
            u16* abh = (u16*)(smc + ABH_OFF);
#pragma unroll
            for (int t = 0; t < 4; t++) {
                int m = m0 + 2 * (lane & 3) + t * 8;
                __half2 h0 = *(__half2*)&av0[t];
                float2 a0 = __half22float2(h0);
                *(u32*)(abh + r * AB_LD + m) =
                    pack_h2(a0.x + sacc[t][0] * corr0, a0.y + sacc[t][1] * corr0);
                __half2 h1 = *(__half2*)&av1[t];
                float2 a1 = __half22float2(h1);
                *(u32*)(abh + (r + 8) * AB_LD + m) =
                    pack_h2(a1.x + sacc[t][2] * corr1, a1.y + sacc[t][3] * corr1);
            }
        }
        __syncthreads();   // ABH ready; X1 (qk) now dead

        // ---- agg = A_hat @ X0 -> X1 (overwrites qk) ----
        agg_tc(smc, smb, acc, warp, lane);
        wstore_hi(smc, acc, X1_OFF, X_LD, warp, lane);
        __syncthreads();

        // ---- fc = agg(X1) @ W_fc^T ----
        wgemm_reg(smb, X1_OFF, g_Wf[l][1][0], acc, warp, lane);
        if (l == 0) {
            // fragment-resident bias + LayerNorm + leaky -> X0
            int rb = lane >> 2;
            int cb = warp * 32 + 2 * (lane & 3);
#pragma unroll
            for (int of = 0; of < 4; of++) {
                float b0 = fcb0[cb + of * 8], b1 = fcb0[cb + of * 8 + 1];
#pragma unroll
                for (int nf = 0; nf < 4; nf++) {
                    float* a = acc + (nf * 4 + of) * 4;
                    a[0] += b0; a[1] += b1; a[2] += b0; a[3] += b1;
                }
            }
            float2* p2 = (float2*)(smc + P2_OFF);
#pragma unroll
            for (int nf = 0; nf < 4; nf++)
#pragma unroll
                for (int rr = 0; rr < 2; rr++) {
                    float s = 0.f, sq = 0.f;
#pragma unroll
                    for (int of = 0; of < 4; of++) {
                        const float* a = acc + (nf * 4 + of) * 4;
                        float x0 = a[rr * 2], x1 = a[rr * 2 + 1];
                        s += x0 + x1;
                        sq += x0 * x0 + x1 * x1;
                    }
#pragma unroll
                    for (int d = 1; d <= 2; d <<= 1) {
                        s += __shfl_xor_sync(0xffffffffu, s, d);
                        sq += __shfl_xor_sync(0xffffffffu, sq, d);
                    }
                    if ((lane & 3) == 0)
                        p2[(nf * 16 + rb + rr * 8) * 8 + warp] = make_float2(s, sq);
                }
            __syncthreads();
            float2* p3 = (float2*)(smc + P3_OFF);
            if (tid < 64) {
                float s = 0.f, sq = 0.f;
#pragma unroll
                for (int w = 0; w < 8; w++) {
                    float2 v = p2[tid * 8 + w];
                    s += v.x; sq += v.y;
                }
                float mean = s * (1.0f / 256.0f);
                float var = sq * (1.0f / 256.0f) - mean * mean;
                p3[tid] = make_float2(mean, rsqrtf(var + 1e-5f));
            }
            __syncthreads();
#pragma unroll
            for (int nf = 0; nf < 4; nf++)
#pragma unroll
                for (int rr = 0; rr < 2; rr++) {
                    int r = nf * 16 + rb + rr * 8;
                    float2 mr = p3[r];
#pragma unroll
                    for (int of = 0; of < 4; of++) {
                        int c = cb + of * 8;
                        const float* a = acc + (nf * 4 + of) * 4;
                        float o0 = (a[rr * 2] - mr.x) * mr.y * ln0_g[c] + ln0_b[c];
                        float o1 = (a[rr * 2 + 1] - mr.x) * mr.y * ln0_g[c + 1] + ln0_b[c + 1];
                        o0 = (o0 >= 0.f) ? o0 : 0.1f * o0;
                        o1 = (o1 >= 0.f) ? o1 : 0.1f * o1;
                        *(u32*)(smc + X0_OFF + (u32)(r * X_LD + c) * 2) = pack_h2(o0, o1);
                    }
                }
            __syncthreads();
        } else {
            wstore_global(acc, out + (size_t)b * 64 * 256, fcb1, warp, lane);
        }
    }
}

extern "C" void kernel_launch(void* const* d_in, const int* in_sizes, int n_in,
                              void* d_out, int out_size)
{
    const float* graph   = (const float*)d_in[0];
    const float* ln_in_g = (const float*)d_in[1];
    const float* ln_in_b = (const float*)d_in[2];
    const float* adj0    = (const float*)d_in[3];
    const float* th0     = (const float*)d_in[4];
    const float* ph0     = (const float*)d_in[5];
    const float* fcw0    = (const float*)d_in[6];
    const float* fcb0    = (const float*)d_in[7];
    const float* ln0_g   = (const float*)d_in[8];
    const float* ln0_b   = (const float*)d_in[9];
    const float* adj1    = (const float*)d_in[10];
    const float* th1     = (const float*)d_in[11];
    const float* ph1     = (const float*)d_in[12];
    const float* fcw1    = (const float*)d_in[13];
    const float* fcb1    = (const float*)d_in[14];
    float* out = (float*)d_out;

    cudaFuncSetAttribute(gconv_kernel,
                         cudaFuncAttributeMaxDynamicSharedMemorySize, SMEM_BYTES);

    prep_kernel<<<520, 512>>>(th0, ph0, fcw0, th1, ph1, fcw1, adj0, adj1);
    gconv_kernel<<<NB, NT, SMEM_BYTES>>>(
        graph, ln_in_g, ln_in_b, fcb0, ln0_g, ln0_b, fcb1, out);
}